// round 5
// baseline (speedup 1.0000x reference)
#include <cuda_runtime.h>
#include <cstdint>

// Problem constants (fixed by the reference setup).
#define BATCH 16
#define SEQ   4096
#define DIM   256          // floats per frame
#define QUADS (DIM / 4)    // 64 float4 per frame

// Scratch (static __device__ arrays; no allocation allowed).
__device__ int2 g_meta [BATCH * SEQ];   // per (b,s): {exclusive start, duration}
__device__ int  g_total[BATCH];         // expanded length per batch

// ---------------------------------------------------------------------------
// Kernel 1: per-batch block scan of durations -> (start, d) meta + totals.
// One block (1024 threads) per batch; each thread owns 4 consecutive s values.
// Triggers programmatic launch completion immediately so the dependent expand
// kernel can start prefetching x while the scan runs.
// ---------------------------------------------------------------------------
__global__ __launch_bounds__(1024) void scan_kernel(
    const int* __restrict__ dims)  // [B, S]
{
    cudaTriggerProgrammaticLaunchCompletion();

    const int b    = blockIdx.x;
    const int tid  = threadIdx.x;          // 0..1023
    const int lane = tid & 31;
    const int warp = tid >> 5;

    const int4 dv = reinterpret_cast<const int4*>(dims + (size_t)b * SEQ)[tid];
    const int sum = dv.x + dv.y + dv.z + dv.w;

    // Inclusive warp scan of per-thread sums.
    int v = sum;
    #pragma unroll
    for (int off = 1; off < 32; off <<= 1) {
        int n = __shfl_up_sync(0xFFFFFFFFu, v, off);
        if (lane >= off) v += n;
    }

    __shared__ int warp_sums[32];
    if (lane == 31) warp_sums[warp] = v;
    __syncthreads();

    if (warp == 0) {
        int w = warp_sums[lane];
        #pragma unroll
        for (int off = 1; off < 32; off <<= 1) {
            int n = __shfl_up_sync(0xFFFFFFFFu, w, off);
            if (lane >= off) w += n;
        }
        warp_sums[lane] = w;   // inclusive scan of warp totals
    }
    __syncthreads();

    const int warp_excl = (warp > 0) ? warp_sums[warp - 1] : 0;
    const int start = warp_excl + (v - sum);   // exclusive prefix before s = tid*4

    // Per-s meta: {start, d} packed as int2; 4 per thread -> two int4 stores.
    int4* mp = reinterpret_cast<int4*>(g_meta + (size_t)b * SEQ) + tid * 2;
    const int s1 = start + dv.x;
    const int s2 = s1 + dv.y;
    const int s3 = s2 + dv.z;
    mp[0] = make_int4(start, dv.x, s1, dv.y);
    mp[1] = make_int4(s2,    dv.z, s3, dv.w);

    if (tid == 0) g_total[b] = warp_sums[31];
}

// ---------------------------------------------------------------------------
// Kernel 2: expand (PDL secondary). Two block roles:
//  - copy blocks: 8 warps/block, one warp per (b,s). The warp PREFETCHES its
//    1KB source row (address independent of the scan) before the grid
//    dependency sync, overlapping the x reads with the scan kernel. After the
//    sync it reads {start, d} and streams the row out d times contiguously.
//  - zero-fill blocks: cover 64-frame stripes of [0,T); write zeros only for
//    frames >= total_b (stripes fully covered by copies exit fast).
// ---------------------------------------------------------------------------
#define NCOPY_BLOCKS ((BATCH * SEQ) / 8)     // 8192
#define ZF_FRAMES    64                      // frames per zero-fill block

__global__ __launch_bounds__(256) void expand_kernel(
    const float* __restrict__ x,   // [B, S, D]
    float* __restrict__ out,       // [B, T, D]
    int T, int zb_per_batch)
{
    const int tid = threadIdx.x;

    if (blockIdx.x < NCOPY_BLOCKS) {
        // ---- copy role ----
        const int warp = tid >> 5;
        const int lane = tid & 31;
        const int g    = blockIdx.x * 8 + warp;      // 0 .. B*SEQ-1
        const int b    = g >> 12;                    // SEQ = 4096

        // Prefetch source row: independent of the scan results.
        const float4* __restrict__ src =
            reinterpret_cast<const float4*>(x) + (size_t)g * QUADS;
        const float4 v0 = __ldg(src + lane);
        const float4 v1 = __ldg(src + lane + 32);

        cudaGridDependencySynchronize();             // wait for scan_kernel

        const int2 meta = __ldg(&g_meta[g]);         // {start, d} broadcast
        const int  d    = meta.y;
        if (d == 0) return;

        float4* __restrict__ o = reinterpret_cast<float4*>(out)
                               + ((size_t)b * T + meta.x) * QUADS;
        for (int c = 0; c < d; c++) {
            __stcs(o + lane,      v0);
            __stcs(o + lane + 32, v1);
            o += QUADS;
        }
    } else {
        // ---- zero-fill role ----
        cudaGridDependencySynchronize();             // needs g_total

        const int zb = blockIdx.x - NCOPY_BLOCKS;
        const int b  = zb / zb_per_batch;
        const int j  = zb - b * zb_per_batch;

        const int total = g_total[b];
        const int base_frame = j * ZF_FRAMES;
        if (base_frame + ZF_FRAMES <= total) return; // fully covered by copies

        const int base = base_frame * QUADS;         // float4 index within batch
        int end = (base_frame + ZF_FRAMES) * QUADS;
        const int tq = T * QUADS;
        if (end > tq) end = tq;
        const int lo = total * QUADS;                // first padding float4

        float4* __restrict__ ob = reinterpret_cast<float4*>(out) + (size_t)b * tq;
        const float4 z = make_float4(0.f, 0.f, 0.f, 0.f);
        for (int e = base + tid; e < end; e += 256)
            if (e >= lo) __stcs(ob + e, z);
    }
}

extern "C" void kernel_launch(void* const* d_in, const int* in_sizes, int n_in,
                              void* d_out, int out_size)
{
    const float* x    = (const float*)d_in[0];   // [B, S, D] float32
    const int*   dims = (const int*)d_in[1];     // [B, S, 1] int32
    float*       out  = (float*)d_out;           // [B, T, D] float32

    const int T = out_size / (BATCH * DIM);
    const int zb_per_batch = (T + ZF_FRAMES - 1) / ZF_FRAMES;

    scan_kernel<<<BATCH, 1024>>>(dims);

    // Launch expand as a PDL secondary: it starts while scan runs, prefetches
    // x, and gates on cudaGridDependencySynchronize() before using scan output.
    cudaLaunchConfig_t cfg = {};
    cfg.gridDim  = dim3(NCOPY_BLOCKS + BATCH * zb_per_batch, 1, 1);
    cfg.blockDim = dim3(256, 1, 1);
    cudaLaunchAttribute attr[1];
    attr[0].id = cudaLaunchAttributeProgrammaticStreamSerialization;
    attr[0].val.programmaticStreamSerializationAllowed = 1;
    cfg.attrs    = attr;
    cfg.numAttrs = 1;
    cudaLaunchKernelEx(&cfg, expand_kernel, x, out, T, zb_per_batch);
}